// round 8
// baseline (speedup 1.0000x reference)
#include <cuda_runtime.h>

#define NN 50000
#define EE 400000
#define HH 4
#define CC 64
#define HC 256   // HH*CC

// ---------------- scratch (device globals: no runtime allocation allowed) ----
__device__ float  g_XL[(size_t)NN * HC];   // source transform  [N,H,C]
__device__ float  g_XR[(size_t)NN * HC];   // target transform  [N,H,C]
__device__ float  g_H1[(size_t)NN * CC];   // layer-1 output
__device__ int    g_deg[NN];               // per-dst degree
__device__ int    g_off[NN + 1];           // CSR offsets
__device__ int    g_cur[NN];               // scatter cursors
__device__ float4 g_edge[EE];              // {src_bits, a0, a1, a2} grouped by dst
__device__ int    g_dhist[64];             // degree-bucket histogram
__device__ int    g_dcur[64];              // degree-bucket cursors
__device__ int    g_nodeord[NN];           // nodes sorted by descending degree

// ---------------- helpers ---------------------------------------------------
__device__ __forceinline__ unsigned long long pk(float lo, float hi) {
    unsigned long long r;
    asm("mov.b64 %0, {%1, %2};" : "=l"(r) : "f"(lo), "f"(hi));
    return r;
}
__device__ __forceinline__ unsigned long long ffma2(unsigned long long a,
                                                    unsigned long long b,
                                                    unsigned long long c) {
    unsigned long long d;
    asm("fma.rn.f32x2 %0, %1, %2, %3;" : "=l"(d) : "l"(a), "l"(b), "l"(c));
    return d;
}
__device__ __forceinline__ float lrelu(float v) { return v > 0.f ? v : 0.2f * v; }

// ---- GEMM: C{0,1}[M,256] = A[M,K] @ W{0,1}[256,K]^T, FFMA2, dual-output ----
__global__ __launch_bounds__(256) void sgemm_dual(
    const float* __restrict__ A,
    const float* __restrict__ W0, const float* __restrict__ W1,
    float* __restrict__ C0, float* __restrict__ C1, int M, int K)
{
    __shared__ float As[16][128];   // [k][m]
    __shared__ float Ws[16][128];   // [k][n]
    const int tid = threadIdx.x;
    const int bm = blockIdx.y * 128;
    const int bx = blockIdx.x;                 // 0..3
    const float* W = (bx < 2) ? W0 : W1;
    float* C       = (bx < 2) ? C0 : C1;
    const int bn = (bx & 1) * 128;
    const int lr = tid >> 2;            // 0..63
    const int lc = (tid & 3) << 2;      // 0,4,8,12
    const int tr = (tid >> 4) << 3;     // 0..120
    const int tc = (tid & 15) << 3;     // 0..120

    unsigned long long acc[4][8];
#pragma unroll
    for (int i = 0; i < 4; i++)
#pragma unroll
        for (int j = 0; j < 8; j++) acc[i][j] = 0ull;

    for (int k0 = 0; k0 < K; k0 += 16) {
#pragma unroll
        for (int i = 0; i < 2; i++) {
            int r = lr + i * 64;
            int gr = bm + r;
            float4 v = make_float4(0.f, 0.f, 0.f, 0.f);
            if (gr < M) v = *(const float4*)(A + (size_t)gr * K + k0 + lc);
            As[lc + 0][r] = v.x; As[lc + 1][r] = v.y;
            As[lc + 2][r] = v.z; As[lc + 3][r] = v.w;
            float4 w = *(const float4*)(W + (size_t)(bn + r) * K + k0 + lc);
            Ws[lc + 0][r] = w.x; Ws[lc + 1][r] = w.y;
            Ws[lc + 2][r] = w.z; Ws[lc + 3][r] = w.w;
        }
        __syncthreads();
#pragma unroll
        for (int k = 0; k < 16; k++) {
            float4 ra0 = *(const float4*)&As[k][tr];
            float4 ra1 = *(const float4*)&As[k][tr + 4];
            float4 rb0 = *(const float4*)&Ws[k][tc];
            float4 rb1 = *(const float4*)&Ws[k][tc + 4];
            union { float4 f; unsigned long long u[2]; } ua0, ua1;
            ua0.f = ra0; ua1.f = ra1;
            unsigned long long rm[4] = { ua0.u[0], ua0.u[1], ua1.u[0], ua1.u[1] };
            float rbf[8] = { rb0.x, rb0.y, rb0.z, rb0.w, rb1.x, rb1.y, rb1.z, rb1.w };
#pragma unroll
            for (int j = 0; j < 8; j++) {
                unsigned long long rn = pk(rbf[j], rbf[j]);
#pragma unroll
                for (int i = 0; i < 4; i++)
                    acc[i][j] = ffma2(rm[i], rn, acc[i][j]);
            }
        }
        __syncthreads();
    }
#pragma unroll
    for (int ip = 0; ip < 4; ip++) {
        float lo[8], hi[8];
#pragma unroll
        for (int j = 0; j < 8; j++) {
            union { unsigned long long u; float f[2]; } t; t.u = acc[ip][j];
            lo[j] = t.f[0]; hi[j] = t.f[1];
        }
        int r0 = bm + tr + 2 * ip;   // pair rows (r0, r0+1), cols bn+tc..+7
        if (r0 < M) {
            float4* p = (float4*)(C + (size_t)r0 * HC + bn + tc);
            p[0] = make_float4(lo[0], lo[1], lo[2], lo[3]);
            p[1] = make_float4(lo[4], lo[5], lo[6], lo[7]);
        }
        if (r0 + 1 < M) {
            float4* p = (float4*)(C + (size_t)(r0 + 1) * HC + bn + tc);
            p[0] = make_float4(hi[0], hi[1], hi[2], hi[3]);
            p[1] = make_float4(hi[4], hi[5], hi[6], hi[7]);
        }
    }
}

// ---------------- CSR build (once per call, reused by both layers) ----------
__global__ void csr_count(const int* __restrict__ dst) {
    int e = blockIdx.x * blockDim.x + threadIdx.x;
    if (e < EE) atomicAdd(&g_deg[dst[e]], 1);
}

// single-block exclusive scan of g_deg -> g_off (+ g_cur copy)
__global__ __launch_bounds__(1024) void csr_scan() {
    __shared__ int ssum[1024];
    const int T = 1024;
    const int per = (NN + T - 1) / T;          // 49
    int t = threadIdx.x;
    int base = t * per;
    int sum = 0;
    for (int i = 0; i < per; i++) {
        int idx = base + i;
        if (idx < NN) sum += g_deg[idx];
    }
    ssum[t] = sum;
    __syncthreads();
    for (int off = 1; off < T; off <<= 1) {
        int u = (t >= off) ? ssum[t - off] : 0;
        __syncthreads();
        ssum[t] += u;
        __syncthreads();
    }
    int run = ssum[t] - sum;                   // exclusive base for this chunk
    for (int i = 0; i < per; i++) {
        int idx = base + i;
        if (idx < NN) {
            g_off[idx] = run;
            g_cur[idx] = run;
            run += g_deg[idx];
        }
    }
    if (t == T - 1) g_off[NN] = run;
}

__global__ void csr_scatter(const int* __restrict__ src,
                            const int* __restrict__ dst,
                            const float* __restrict__ ea) {
    int e = blockIdx.x * blockDim.x + threadIdx.x;
    if (e >= EE) return;
    int d = dst[e];
    int p = atomicAdd(&g_cur[d], 1);
    float4 r;
    r.x = __int_as_float(src[e]);
    r.y = ea[(size_t)e * 3 + 0];
    r.z = ea[(size_t)e * 3 + 1];
    r.w = ea[(size_t)e * 3 + 2];
    g_edge[p] = r;
}

// ---------------- degree-descending node order -------------------------------
__device__ __forceinline__ int deg_bucket(int deg) {
    return (deg > 63) ? 0 : (63 - deg);        // bucket 0 = largest degree
}
__global__ void deg_hist() {
    __shared__ int sh[64];
    int t = threadIdx.x;
    if (t < 64) sh[t] = 0;
    __syncthreads();
    int n = blockIdx.x * blockDim.x + t;
    if (n < NN) atomicAdd(&sh[deg_bucket(g_off[n + 1] - g_off[n])], 1);
    __syncthreads();
    if (t < 64 && sh[t]) atomicAdd(&g_dhist[t], sh[t]);
}
__global__ void deg_scan() {                    // 1 block, 64 threads
    __shared__ int s[64];
    int t = threadIdx.x;
    int my = g_dhist[t];
    s[t] = my;
    __syncthreads();
    for (int off = 1; off < 64; off <<= 1) {
        int u = (t >= off) ? s[t - off] : 0;
        __syncthreads();
        s[t] += u;
        __syncthreads();
    }
    g_dcur[t] = s[t] - my;                      // exclusive base as cursor
}
__global__ void deg_scatter() {
    int n = blockIdx.x * blockDim.x + threadIdx.x;
    if (n >= NN) return;
    int pos = atomicAdd(&g_dcur[deg_bucket(g_off[n + 1] - g_off[n])], 1);
    g_nodeord[pos] = n;
}

// ---- fused gather pass: TWO warps per dst node, software-pipelined ----------
// Warp (node, pair): pair owns heads {2*pair, 2*pair+1}. Lane: sub = lane>>4
// selects head within pair, g = lane&15 owns channels [4g, 4g+4) of that head
// (flat channel f = head*64 + 4g). Logit reduce = 4-level butterfly within the
// 16-lane head group. Head-pair combine via shfl_xor(16); cross-pair combine
// via 1KB smem + one block sync (block = exactly 4 nodes, 50000 % 4 == 0, so
// no divergent early returns around __syncthreads).
// Edge records prefetched 2 ahead, xl rows 1 ahead to hide the er->xl L2 chain.
// Softmax ratio is shift-invariant and logits are O(10), so exp() without the
// segment-max shift is exact enough in fp32 (validated: rel_err ~2.8e-7).
__global__ __launch_bounds__(256) void node_gather(
    const float* __restrict__ We,       // [256,3]
    const float* __restrict__ att,      // [256] flat h*64+c
    const float* __restrict__ bias,     // [64]
    const float* __restrict__ prelu,    // [64]
    float* __restrict__ out, int mode)
{
    __shared__ float sp[4][64];
    const int tid  = threadIdx.x;
    const int warp = tid >> 5;          // 0..7
    const int slot = warp >> 1;         // node slot in block, 0..3
    const int pair = warp & 1;          // head pair 0/1
    const int lane = tid & 31;
    const int sub  = lane >> 4;         // head within pair
    const int g    = lane & 15;         // channel group
    const int head = pair * 2 + sub;
    const int f    = head * 64 + g * 4; // flat channel base (f*3 % 4 == 0)

    const int n = g_nodeord[blockIdx.x * 4 + slot];

    // per-lane params: We rows f..f+3 (row stride 3), att[f..f+3]
    const float4* wp = reinterpret_cast<const float4*>(We + f * 3);
    float4 q0 = __ldg(wp);
    float4 q1 = __ldg(wp + 1);
    float4 q2 = __ldg(wp + 2);
    // channel i coefficients: (wa,wb,wc)
    const float wa0 = q0.x, wb0 = q0.y, wc0 = q0.z;
    const float wa1 = q0.w, wb1 = q1.x, wc1 = q1.y;
    const float wa2 = q1.z, wb2 = q1.w, wc2 = q2.x;
    const float wa3 = q2.y, wb3 = q2.z, wc3 = q2.w;
    const float4 av = __ldg((const float4*)(att + f));
    const float4 xr = __ldg((const float4*)(g_XR + (size_t)n * HC + f));

    const int o0 = g_off[n];
    const int cnt = g_off[n + 1] - o0;
    const int foff = f >> 2;
    const float4* XLb = reinterpret_cast<const float4*>(g_XL);

    float4 acc = make_float4(0.f, 0.f, 0.f, 0.f);
    float den = 0.f;

    if (cnt > 0) {
        float4 erA = __ldg(&g_edge[o0]);
        float4 erB = (cnt > 1) ? __ldg(&g_edge[o0 + 1]) : erA;
        float4 XA  = __ldg(XLb + (size_t)__float_as_int(erA.x) * 64 + foff);
        for (int j = 0; j < cnt; j++) {
            // prefetch: edge record 2 ahead, xl row 1 ahead
            float4 erC = (j + 2 < cnt) ? __ldg(&g_edge[o0 + j + 2]) : erB;
            float4 XB  = (j + 1 < cnt)
                       ? __ldg(XLb + (size_t)__float_as_int(erB.x) * 64 + foff)
                       : XA;
            float z0 = lrelu(XA.x + xr.x + fmaf(erA.w, wc0, fmaf(erA.z, wb0, erA.y * wa0)));
            float z1 = lrelu(XA.y + xr.y + fmaf(erA.w, wc1, fmaf(erA.z, wb1, erA.y * wa1)));
            float z2 = lrelu(XA.z + xr.z + fmaf(erA.w, wc2, fmaf(erA.z, wb2, erA.y * wa2)));
            float z3 = lrelu(XA.w + xr.w + fmaf(erA.w, wc3, fmaf(erA.z, wb3, erA.y * wa3)));
            float p = fmaf(z0, av.x, fmaf(z1, av.y, fmaf(z2, av.z, z3 * av.w)));
            // butterfly within the 16-lane head group
            p += __shfl_xor_sync(0xffffffffu, p, 8);
            p += __shfl_xor_sync(0xffffffffu, p, 4);
            p += __shfl_xor_sync(0xffffffffu, p, 2);
            p += __shfl_xor_sync(0xffffffffu, p, 1);
            float w = __expf(p);
            den += w;
            acc.x = fmaf(w, XA.x, acc.x);
            acc.y = fmaf(w, XA.y, acc.y);
            acc.z = fmaf(w, XA.z, acc.z);
            acc.w = fmaf(w, XA.w, acc.w);
            erA = erB; erB = erC; XA = XB;
        }
    }

    // normalize this head (zero-degree -> 0, matching segment_sum semantics)
    float inv = den > 0.f ? __frcp_rn(den) : 0.f;
    acc.x *= inv; acc.y *= inv; acc.z *= inv; acc.w *= inv;

    // combine the two heads of this pair: lanes g and g+16 hold the same
    // output channels c = 4g..4g+3
    acc.x += __shfl_xor_sync(0xffffffffu, acc.x, 16);
    acc.y += __shfl_xor_sync(0xffffffffu, acc.y, 16);
    acc.z += __shfl_xor_sync(0xffffffffu, acc.z, 16);
    acc.w += __shfl_xor_sync(0xffffffffu, acc.w, 16);

    // cross-pair combine via smem
    if (pair == 0 && lane < 16)
        ((float4*)sp[slot])[g] = acc;
    __syncthreads();
    if (pair == 1 && lane < 16) {
        float4 o = ((float4*)sp[slot])[g];
        o.x += acc.x; o.y += acc.y; o.z += acc.z; o.w += acc.w;
        float4 bv = __ldg((const float4*)(bias + 4 * g));
        float4 v;
        v.x = fmaf(0.25f, o.x, bv.x);
        v.y = fmaf(0.25f, o.y, bv.y);
        v.z = fmaf(0.25f, o.z, bv.z);
        v.w = fmaf(0.25f, o.w, bv.w);
        if (mode == 0) {
            *(float4*)(g_H1 + (size_t)n * CC + 4 * g) = v;
        } else {
            float4 pw = __ldg((const float4*)(prelu + 4 * g));
            v.x = (v.x >= 0.f) ? v.x : pw.x * v.x;
            v.y = (v.y >= 0.f) ? v.y : pw.y * v.y;
            v.z = (v.z >= 0.f) ? v.z : pw.z * v.z;
            v.w = (v.w >= 0.f) ? v.w : pw.w * v.w;
            *(float4*)(out + (size_t)n * CC + 4 * g) = v;
        }
    }
}

// ---------------- launch -----------------------------------------------------
extern "C" void kernel_launch(void* const* d_in, const int* in_sizes, int n_in,
                              void* d_out, int out_size)
{
    const float* x     = (const float*)d_in[0];
    const int*   ei    = (const int*)  d_in[1];
    const float* eattr = (const float*)d_in[2];
    const float* Wl1   = (const float*)d_in[3];
    const float* Wr1   = (const float*)d_in[4];
    const float* We1   = (const float*)d_in[5];
    const float* att1  = (const float*)d_in[6];
    const float* b1    = (const float*)d_in[7];
    const float* Wl2   = (const float*)d_in[8];
    const float* Wr2   = (const float*)d_in[9];
    const float* We2   = (const float*)d_in[10];
    const float* att2  = (const float*)d_in[11];
    const float* b2    = (const float*)d_in[12];
    const float* prelu = (const float*)d_in[13];
    float* out = (float*)d_out;

    const int* src = ei;
    const int* dst = ei + EE;

    float *XL, *XR, *H1;
    void *degp, *dhistp;
    cudaGetSymbolAddress((void**)&XL, g_XL);
    cudaGetSymbolAddress((void**)&XR, g_XR);
    cudaGetSymbolAddress((void**)&H1, g_H1);
    cudaGetSymbolAddress(&degp, g_deg);
    cudaGetSymbolAddress(&dhistp, g_dhist);

    dim3 ggrid(4, (NN + 127) / 128);
    const int egrid = (EE + 255) / 256;
    const int ngrid = NN / 4;              // 12500, exact
    const int vgrid = (NN + 255) / 256;

    // ---- CSR build + degree-sorted node order (shared by both layers) ----
    cudaMemsetAsync(degp, 0, NN * sizeof(int));
    cudaMemsetAsync(dhistp, 0, 64 * sizeof(int));
    csr_count<<<egrid, 256>>>(dst);
    csr_scan<<<1, 1024>>>();
    csr_scatter<<<egrid, 256>>>(src, dst, eattr);
    deg_hist<<<vgrid, 256>>>();
    deg_scan<<<1, 64>>>();
    deg_scatter<<<vgrid, 256>>>();

    // ---- layer 1 ----
    sgemm_dual<<<ggrid, 256>>>(x, Wl1, Wr1, XL, XR, NN, 128);
    node_gather<<<ngrid, 256>>>(We1, att1, b1, prelu, out, 0);

    // ---- layer 2 ----
    sgemm_dual<<<ggrid, 256>>>(H1, Wl2, Wr2, XL, XR, NN, 64);
    node_gather<<<ngrid, 256>>>(We2, att2, b2, prelu, out, 1);
}

// round 11
// speedup vs baseline: 1.1045x; 1.1045x over previous
#include <cuda_runtime.h>
#include <cuda_bf16.h>
#include <mma.h>
#include <cstdint>

using namespace nvcuda;

#define NN 50000
#define NN_PAD 50048   // 391 * 128, for unguarded wmma stores into scratch
#define EE 400000
#define HH 4
#define CC 64
#define HC 256   // HH*CC

// GEMM tiling
#define BM 128
#define BN 64
#define BK 32
#define ASTR 40        // smem row stride (bf16 elems): 80B, conflict-free ldmatrix

// ---------------- scratch (device globals: no runtime allocation allowed) ----
__device__ float  g_XL[(size_t)NN_PAD * HC];  // source transform  [N,H,C]
__device__ float  g_XR[(size_t)NN_PAD * HC];  // target transform  [N,H,C]
__device__ float  g_H1[(size_t)NN_PAD * CC];  // layer-1 output
__device__ int    g_deg[NN];                  // per-dst degree
__device__ int    g_off[NN + 1];              // CSR offsets
__device__ int    g_cur[NN];                  // scatter cursors
__device__ float4 g_edge[EE];                 // {src_bits, a0,a1,a2} grouped by dst
__device__ int    g_dhist[64];                // degree-bucket histogram
__device__ int    g_dcur[64];                 // degree-bucket cursors
__device__ int    g_nodeord[NN];              // nodes sorted by descending degree

// ---------------- helpers ---------------------------------------------------
__device__ __forceinline__ float lrelu(float v) { return v > 0.f ? v : 0.2f * v; }

__device__ __forceinline__ void split_bf16(float2 v, __nv_bfloat162& hi,
                                           __nv_bfloat162& lo) {
    __nv_bfloat16 hx = __float2bfloat16(v.x);
    __nv_bfloat16 hy = __float2bfloat16(v.y);
    hi.x = hx; hi.y = hy;
    lo.x = __float2bfloat16(v.x - __bfloat162float(hx));
    lo.y = __float2bfloat16(v.y - __bfloat162float(hy));
}

// ---- GEMM: C{0,1}[M,256] = A[M,K] @ W{0,1}[256,K]^T ------------------------
// bf16 3-term split (Ahi*Whi + Ahi*Wlo + Alo*Whi), fp32 wmma accumulators.
// CTA: 128x64 tile, 8 warps (4 in M x 2 in N, 32x32 each). grid.x: 0-3 -> W0,
// 4-7 -> W1 (n offset (bx&3)*64). C rows padded to NN_PAD -> unguarded stores.
__global__ __launch_bounds__(256) void gemm_wmma(
    const float* __restrict__ A,
    const float* __restrict__ W0, const float* __restrict__ W1,
    float* __restrict__ C0, float* __restrict__ C1, int M, int K)
{
    __shared__ __align__(16) __nv_bfloat16 sAhi[BM * ASTR];
    __shared__ __align__(16) __nv_bfloat16 sAlo[BM * ASTR];
    __shared__ __align__(16) __nv_bfloat16 sWhi[BN * ASTR];
    __shared__ __align__(16) __nv_bfloat16 sWlo[BN * ASTR];

    const int tid  = threadIdx.x;
    const int warp = tid >> 5;
    const int bx   = blockIdx.x;                  // 0..7
    const float* W = (bx < 4) ? W0 : W1;
    float* C       = (bx < 4) ? C0 : C1;
    const int bn   = (bx & 3) * BN;
    const int bm   = blockIdx.y * BM;
    const int wm   = (warp & 3) * 32;             // warp M offset in tile
    const int wn   = (warp >> 2) * 32;            // warp N offset in tile

    wmma::fragment<wmma::accumulator, 16, 16, 16, float> acc[2][2];
#pragma unroll
    for (int i = 0; i < 2; i++)
#pragma unroll
        for (int j = 0; j < 2; j++) wmma::fill_fragment(acc[i][j], 0.f);

    const int nch = K / BK;
    for (int ch = 0; ch < nch; ch++) {
        // stage A chunk: BM x BK fp32 -> hi/lo bf16 (guarded rows)
        for (int i = tid; i < BM * BK / 2; i += 256) {
            int row = i >> 4;
            int cp  = (i & 15) * 2;
            int gr  = bm + row;
            float2 v = make_float2(0.f, 0.f);
            if (gr < M) v = *(const float2*)(A + (size_t)gr * K + ch * BK + cp);
            __nv_bfloat162 h2, l2;
            split_bf16(v, h2, l2);
            *(__nv_bfloat162*)&sAhi[row * ASTR + cp] = h2;
            *(__nv_bfloat162*)&sAlo[row * ASTR + cp] = l2;
        }
        // stage W chunk: BN x BK fp32 -> hi/lo bf16 (rows always in range)
        for (int i = tid; i < BN * BK / 2; i += 256) {
            int row = i >> 4;
            int cp  = (i & 15) * 2;
            float2 v = *(const float2*)(W + (size_t)(bn + row) * K + ch * BK + cp);
            __nv_bfloat162 h2, l2;
            split_bf16(v, h2, l2);
            *(__nv_bfloat162*)&sWhi[row * ASTR + cp] = h2;
            *(__nv_bfloat162*)&sWlo[row * ASTR + cp] = l2;
        }
        __syncthreads();

#pragma unroll
        for (int ks = 0; ks < BK; ks += 16) {
            wmma::fragment<wmma::matrix_a, 16, 16, 16, __nv_bfloat16, wmma::row_major> ahi[2], alo[2];
            wmma::fragment<wmma::matrix_b, 16, 16, 16, __nv_bfloat16, wmma::col_major> bhi[2], blo[2];
#pragma unroll
            for (int i = 0; i < 2; i++) {
                wmma::load_matrix_sync(ahi[i], &sAhi[(wm + 16 * i) * ASTR + ks], ASTR);
                wmma::load_matrix_sync(alo[i], &sAlo[(wm + 16 * i) * ASTR + ks], ASTR);
                wmma::load_matrix_sync(bhi[i], &sWhi[(wn + 16 * i) * ASTR + ks], ASTR);
                wmma::load_matrix_sync(blo[i], &sWlo[(wn + 16 * i) * ASTR + ks], ASTR);
            }
#pragma unroll
            for (int i = 0; i < 2; i++)
#pragma unroll
                for (int j = 0; j < 2; j++) {
                    wmma::mma_sync(acc[i][j], ahi[i], bhi[j], acc[i][j]);
                    wmma::mma_sync(acc[i][j], ahi[i], blo[j], acc[i][j]);
                    wmma::mma_sync(acc[i][j], alo[i], bhi[j], acc[i][j]);
                }
        }
        __syncthreads();
    }

    // epilogue: unguarded stores (C buffers padded to NN_PAD rows)
#pragma unroll
    for (int i = 0; i < 2; i++)
#pragma unroll
        for (int j = 0; j < 2; j++)
            wmma::store_matrix_sync(C + (size_t)(bm + wm + 16 * i) * HC + bn + wn + 16 * j,
                                    acc[i][j], HC, wmma::mem_row_major);
}

// ---------------- CSR build (once per call, reused by both layers) ----------
__global__ void csr_count(const int* __restrict__ dst) {
    int e = blockIdx.x * blockDim.x + threadIdx.x;
    if (e < EE) atomicAdd(&g_deg[dst[e]], 1);
}

__global__ __launch_bounds__(1024) void csr_scan() {
    __shared__ int ssum[1024];
    const int T = 1024;
    const int per = (NN + T - 1) / T;
    int t = threadIdx.x;
    int base = t * per;
    int sum = 0;
    for (int i = 0; i < per; i++) {
        int idx = base + i;
        if (idx < NN) sum += g_deg[idx];
    }
    ssum[t] = sum;
    __syncthreads();
    for (int off = 1; off < T; off <<= 1) {
        int u = (t >= off) ? ssum[t - off] : 0;
        __syncthreads();
        ssum[t] += u;
        __syncthreads();
    }
    int run = ssum[t] - sum;
    for (int i = 0; i < per; i++) {
        int idx = base + i;
        if (idx < NN) {
            g_off[idx] = run;
            g_cur[idx] = run;
            run += g_deg[idx];
        }
    }
    if (t == T - 1) g_off[NN] = run;
}

__global__ void csr_scatter(const int* __restrict__ src,
                            const int* __restrict__ dst,
                            const float* __restrict__ ea) {
    int e = blockIdx.x * blockDim.x + threadIdx.x;
    if (e >= EE) return;
    int d = dst[e];
    int p = atomicAdd(&g_cur[d], 1);
    float4 r;
    r.x = __int_as_float(src[e]);
    r.y = ea[(size_t)e * 3 + 0];
    r.z = ea[(size_t)e * 3 + 1];
    r.w = ea[(size_t)e * 3 + 2];
    g_edge[p] = r;
}

// ---------------- degree-descending node order -------------------------------
__device__ __forceinline__ int deg_bucket(int deg) {
    return (deg > 63) ? 0 : (63 - deg);
}
__global__ void deg_hist() {
    __shared__ int sh[64];
    int t = threadIdx.x;
    if (t < 64) sh[t] = 0;
    __syncthreads();
    int n = blockIdx.x * blockDim.x + t;
    if (n < NN) atomicAdd(&sh[deg_bucket(g_off[n + 1] - g_off[n])], 1);
    __syncthreads();
    if (t < 64 && sh[t]) atomicAdd(&g_dhist[t], sh[t]);
}
__global__ void deg_scan() {
    __shared__ int s[64];
    int t = threadIdx.x;
    int my = g_dhist[t];
    s[t] = my;
    __syncthreads();
    for (int off = 1; off < 64; off <<= 1) {
        int u = (t >= off) ? s[t - off] : 0;
        __syncthreads();
        s[t] += u;
        __syncthreads();
    }
    g_dcur[t] = s[t] - my;
}
__global__ void deg_scatter() {
    int n = blockIdx.x * blockDim.x + threadIdx.x;
    if (n >= NN) return;
    int pos = atomicAdd(&g_dcur[deg_bucket(g_off[n + 1] - g_off[n])], 1);
    g_nodeord[pos] = n;
}

// ---- fused gather pass: one warp per dst node, lane = head*8 + group --------
// (R7 version — proven fastest.) Lane l owns channels [8l, 8l+8) of the flat
// [H*C] row (head = l>>3). Logit reduce = one 8-lane butterfly + 1 expf.
// Softmax ratio is shift-invariant and logits are O(10), so exp() without the
// segment-max shift is exact enough in fp32.
__global__ __launch_bounds__(256) void node_gather(
    const float* __restrict__ We,       // [256,3]
    const float* __restrict__ att,      // [256] flat h*64+c
    const float* __restrict__ bias,     // [64]
    const float* __restrict__ prelu,    // [64]
    float* __restrict__ out, int mode)
{
    int tid = threadIdx.x;
    int widx = blockIdx.x * 8 + (tid >> 5);
    if (widx >= NN) return;
    int lane = tid & 31;
    int n = g_nodeord[widx];
    int f = lane * 8;

    float wa[8], wb[8], wc[8], av[8];
    {
        const float4* wp = reinterpret_cast<const float4*>(We + f * 3);
        float4 q[6];
#pragma unroll
        for (int i = 0; i < 6; i++) q[i] = __ldg(wp + i);
        const float* qf = (const float*)q;
#pragma unroll
        for (int i = 0; i < 8; i++) {
            wa[i] = qf[3 * i + 0];
            wb[i] = qf[3 * i + 1];
            wc[i] = qf[3 * i + 2];
        }
        float4 A0 = __ldg((const float4*)(att + f));
        float4 A1 = __ldg((const float4*)(att + f + 4));
        av[0] = A0.x; av[1] = A0.y; av[2] = A0.z; av[3] = A0.w;
        av[4] = A1.x; av[5] = A1.y; av[6] = A1.z; av[7] = A1.w;
    }

    const float4* xrp = reinterpret_cast<const float4*>(g_XR) + (size_t)n * (HC / 4);
    float4 R0 = __ldg(xrp + 2 * lane);
    float4 R1 = __ldg(xrp + 2 * lane + 1);
    float xr[8] = { R0.x, R0.y, R0.z, R0.w, R1.x, R1.y, R1.z, R1.w };

    int o0 = g_off[n];
    int o1 = g_off[n + 1];

    float acc[8] = { 0.f, 0.f, 0.f, 0.f, 0.f, 0.f, 0.f, 0.f };
    float den = 0.f;

    for (int j = o0; j < o1; j++) {
        float4 er = __ldg(&g_edge[j]);
        int s = __float_as_int(er.x);
        const float4* xlp = reinterpret_cast<const float4*>(g_XL) + (size_t)s * (HC / 4);
        float4 X0 = __ldg(xlp + 2 * lane);
        float4 X1 = __ldg(xlp + 2 * lane + 1);
        float xl[8] = { X0.x, X0.y, X0.z, X0.w, X1.x, X1.y, X1.z, X1.w };

        float p = 0.f;
#pragma unroll
        for (int i = 0; i < 8; i++) {
            float z = lrelu(xl[i] + xr[i] +
                            fmaf(er.w, wc[i], fmaf(er.z, wb[i], er.y * wa[i])));
            p = fmaf(z, av[i], p);
        }
        p += __shfl_xor_sync(0xffffffffu, p, 4);
        p += __shfl_xor_sync(0xffffffffu, p, 2);
        p += __shfl_xor_sync(0xffffffffu, p, 1);
        float w = __expf(p);
        den += w;
#pragma unroll
        for (int i = 0; i < 8; i++) acc[i] = fmaf(w, xl[i], acc[i]);
    }

    float inv = den > 0.f ? __frcp_rn(den) : 0.f;
#pragma unroll
    for (int i = 0; i < 8; i++) acc[i] *= inv;

#pragma unroll
    for (int i = 0; i < 8; i++) {
        acc[i] += __shfl_xor_sync(0xffffffffu, acc[i], 8);
        acc[i] += __shfl_xor_sync(0xffffffffu, acc[i], 16);
    }

    if (lane < 8) {
        int c = lane * 8;
        float4 b0 = __ldg((const float4*)(bias + c));
        float4 b1 = __ldg((const float4*)(bias + c + 4));
        float v[8];
        v[0] = fmaf(0.25f, acc[0], b0.x);
        v[1] = fmaf(0.25f, acc[1], b0.y);
        v[2] = fmaf(0.25f, acc[2], b0.z);
        v[3] = fmaf(0.25f, acc[3], b0.w);
        v[4] = fmaf(0.25f, acc[4], b1.x);
        v[5] = fmaf(0.25f, acc[5], b1.y);
        v[6] = fmaf(0.25f, acc[6], b1.z);
        v[7] = fmaf(0.25f, acc[7], b1.w);
        if (mode == 0) {
            float4* p = (float4*)(g_H1 + (size_t)n * CC + c);
            p[0] = make_float4(v[0], v[1], v[2], v[3]);
            p[1] = make_float4(v[4], v[5], v[6], v[7]);
        } else {
            float4 p0 = __ldg((const float4*)(prelu + c));
            float4 p1 = __ldg((const float4*)(prelu + c + 4));
            float pw[8] = { p0.x, p0.y, p0.z, p0.w, p1.x, p1.y, p1.z, p1.w };
#pragma unroll
            for (int i = 0; i < 8; i++) v[i] = (v[i] >= 0.f) ? v[i] : pw[i] * v[i];
            float4* p = (float4*)(out + (size_t)n * CC + c);
            p[0] = make_float4(v[0], v[1], v[2], v[3]);
            p[1] = make_float4(v[4], v[5], v[6], v[7]);
        }
    }
}

// ---------------- launch -----------------------------------------------------
extern "C" void kernel_launch(void* const* d_in, const int* in_sizes, int n_in,
                              void* d_out, int out_size)
{
    const float* x     = (const float*)d_in[0];
    const int*   ei    = (const int*)  d_in[1];
    const float* eattr = (const float*)d_in[2];
    const float* Wl1   = (const float*)d_in[3];
    const float* Wr1   = (const float*)d_in[4];
    const float* We1   = (const float*)d_in[5];
    const float* att1  = (const float*)d_in[6];
    const float* b1    = (const float*)d_in[7];
    const float* Wl2   = (const float*)d_in[8];
    const float* Wr2   = (const float*)d_in[9];
    const float* We2   = (const float*)d_in[10];
    const float* att2  = (const float*)d_in[11];
    const float* b2    = (const float*)d_in[12];
    const float* prelu = (const float*)d_in[13];
    float* out = (float*)d_out;

    const int* src = ei;
    const int* dst = ei + EE;

    float *XL, *XR, *H1;
    void *degp, *dhistp;
    cudaGetSymbolAddress((void**)&XL, g_XL);
    cudaGetSymbolAddress((void**)&XR, g_XR);
    cudaGetSymbolAddress((void**)&H1, g_H1);
    cudaGetSymbolAddress(&degp, g_deg);
    cudaGetSymbolAddress(&dhistp, g_dhist);

    dim3 ggrid(8, NN_PAD / BM);            // 8 x 391
    const int egrid = (EE + 255) / 256;
    const int ngrid = (NN + 7) / 8;
    const int vgrid = (NN + 255) / 256;

    // ---- CSR build + degree-sorted node order (shared by both layers) ----
    cudaMemsetAsync(degp, 0, NN * sizeof(int));
    cudaMemsetAsync(dhistp, 0, 64 * sizeof(int));
    csr_count<<<egrid, 256>>>(dst);
    csr_scan<<<1, 1024>>>();
    csr_scatter<<<egrid, 256>>>(src, dst, eattr);
    deg_hist<<<vgrid, 256>>>();
    deg_scan<<<1, 64>>>();
    deg_scatter<<<vgrid, 256>>>();

    // ---- layer 1 ----
    gemm_wmma<<<ggrid, 256>>>(x, Wl1, Wr1, XL, XR, NN, 128);
    node_gather<<<ngrid, 256>>>(We1, att1, b1, prelu, out, 0);

    // ---- layer 2 ----
    gemm_wmma<<<ggrid, 256>>>(H1, Wl2, Wr2, XL, XR, NN, 64);
    node_gather<<<ngrid, 256>>>(We2, att2, b2, prelu, out, 1);
}

// round 13
// speedup vs baseline: 1.2288x; 1.1125x over previous
#include <cuda_runtime.h>
#include <cuda_bf16.h>
#include <mma.h>
#include <cstdint>

using namespace nvcuda;

#define NN 50000
#define NN_PAD 50048   // 391 * 128, for unguarded wmma stores into scratch
#define EE 400000
#define HH 4
#define CC 64
#define HC 256   // HH*CC

// GEMM tiling
#define BM 128
#define BN 64
#define BK 64
#define ASTR 72        // smem row stride (bf16): 144B, 16B-aligned, conflict-free
#define GSMEM ((BM * ASTR * 2 + BN * ASTR * 2) * 2)   // 55296 B

// ---------------- scratch (device globals: no runtime allocation allowed) ----
__device__ float  g_XL[(size_t)NN_PAD * HC];  // source transform  [N,H,C]
__device__ float  g_XR[(size_t)NN_PAD * HC];  // target transform  [N,H,C]
__device__ float  g_H1[(size_t)NN_PAD * CC];  // layer-1 output
__device__ __nv_bfloat16 g_Ahi[(size_t)NN_PAD * 128];
__device__ __nv_bfloat16 g_Alo[(size_t)NN_PAD * 128];
__device__ __nv_bfloat16 g_Whi[2 * 256 * 128];
__device__ __nv_bfloat16 g_Wlo[2 * 256 * 128];
__device__ int    g_deg[NN];                  // per-dst degree
__device__ int    g_off[NN + 1];              // CSR offsets
__device__ int    g_cur[NN];                  // scatter cursors
__device__ float4 g_edge[EE];                 // {src_bits, a0,a1,a2} grouped by dst
__device__ int    g_dhist[64];                // degree-bucket histogram
__device__ int    g_dcur[64];                 // degree-bucket cursors
__device__ int    g_nodeord[NN];              // nodes sorted by descending degree

// ---------------- helpers ---------------------------------------------------
__device__ __forceinline__ float lrelu(float v) { return v > 0.f ? v : 0.2f * v; }

// ---- split fp32 matrix into bf16 hi/lo (Markidis). Pads with zeros. --------
__global__ void split_mat(const float* __restrict__ A,
                          __nv_bfloat16* __restrict__ hi,
                          __nv_bfloat16* __restrict__ lo,
                          int quads_real, int quads_total)
{
    int i = blockIdx.x * blockDim.x + threadIdx.x;
    if (i >= quads_total) return;
    float4 v = (i < quads_real) ? ((const float4*)A)[i]
                                : make_float4(0.f, 0.f, 0.f, 0.f);
    __nv_bfloat162 h0, h1, l0, l1;
    h0.x = __float2bfloat16(v.x);  h0.y = __float2bfloat16(v.y);
    h1.x = __float2bfloat16(v.z);  h1.y = __float2bfloat16(v.w);
    l0.x = __float2bfloat16(v.x - __bfloat162float(h0.x));
    l0.y = __float2bfloat16(v.y - __bfloat162float(h0.y));
    l1.x = __float2bfloat16(v.z - __bfloat162float(h1.x));
    l1.y = __float2bfloat16(v.w - __bfloat162float(h1.y));
    ((__nv_bfloat162*)hi)[2 * i]     = h0;
    ((__nv_bfloat162*)hi)[2 * i + 1] = h1;
    ((__nv_bfloat162*)lo)[2 * i]     = l0;
    ((__nv_bfloat162*)lo)[2 * i + 1] = l1;
}

// ---- GEMM: C{0,1}[M,256] = A[M,K] @ W{0,1}[256,K]^T ------------------------
// Inputs pre-split to bf16 hi/lo. 3-term: Ahi*Whi + Ahi*Wlo + Alo*Whi, fp32
// accumulate. CTA: 128x64 tile, 8 warps (4M x 2N, 32x32 each). grid.x 0-3 ->
// W slab 0, 4-7 -> W slab 1 (offset 256*K in g_Whi/g_Wlo); n = (bx&3)*64.
// C rows padded to NN_PAD -> unguarded wmma stores.
__global__ __launch_bounds__(256) void gemm_wmma(
    const __nv_bfloat16* __restrict__ Ahi, const __nv_bfloat16* __restrict__ Alo,
    const __nv_bfloat16* __restrict__ Whi, const __nv_bfloat16* __restrict__ Wlo,
    float* __restrict__ C0, float* __restrict__ C1, int K)
{
    extern __shared__ __nv_bfloat16 sm[];
    __nv_bfloat16* sAhi = sm;
    __nv_bfloat16* sAlo = sAhi + BM * ASTR;
    __nv_bfloat16* sWhi = sAlo + BM * ASTR;
    __nv_bfloat16* sWlo = sWhi + BN * ASTR;

    const int tid  = threadIdx.x;
    const int warp = tid >> 5;
    const int bx   = blockIdx.x;                  // 0..7
    const size_t woff = (bx < 4) ? 0 : (size_t)256 * K;
    float* C       = (bx < 4) ? C0 : C1;
    const int bn   = (bx & 3) * BN;
    const int bm   = blockIdx.y * BM;
    const int wm   = (warp & 3) * 32;
    const int wn   = (warp >> 2) * 32;

    wmma::fragment<wmma::accumulator, 16, 16, 16, float> acc[2][2];
#pragma unroll
    for (int i = 0; i < 2; i++)
#pragma unroll
        for (int j = 0; j < 2; j++) wmma::fill_fragment(acc[i][j], 0.f);

    const int nch = K / BK;
    for (int ch = 0; ch < nch; ch++) {
        // stage A: BM x BK bf16 hi/lo (uint4 = 8 bf16)
        for (int i = tid; i < BM * BK / 8; i += 256) {
            int row = i >> 3;
            int c8  = (i & 7) * 8;
            size_t gsrc = (size_t)(bm + row) * K + ch * BK + c8;
            *(uint4*)&sAhi[row * ASTR + c8] = *(const uint4*)(Ahi + gsrc);
            *(uint4*)&sAlo[row * ASTR + c8] = *(const uint4*)(Alo + gsrc);
        }
        // stage W: BN x BK bf16 hi/lo
        for (int i = tid; i < BN * BK / 8; i += 256) {
            int row = i >> 3;
            int c8  = (i & 7) * 8;
            size_t gsrc = woff + (size_t)(bn + row) * K + ch * BK + c8;
            *(uint4*)&sWhi[row * ASTR + c8] = *(const uint4*)(Whi + gsrc);
            *(uint4*)&sWlo[row * ASTR + c8] = *(const uint4*)(Wlo + gsrc);
        }
        __syncthreads();

#pragma unroll
        for (int ks = 0; ks < BK; ks += 16) {
            wmma::fragment<wmma::matrix_a, 16, 16, 16, __nv_bfloat16, wmma::row_major> ahi[2], alo[2];
            wmma::fragment<wmma::matrix_b, 16, 16, 16, __nv_bfloat16, wmma::col_major> bhi[2], blo[2];
#pragma unroll
            for (int i = 0; i < 2; i++) {
                wmma::load_matrix_sync(ahi[i], &sAhi[(wm + 16 * i) * ASTR + ks], ASTR);
                wmma::load_matrix_sync(alo[i], &sAlo[(wm + 16 * i) * ASTR + ks], ASTR);
                wmma::load_matrix_sync(bhi[i], &sWhi[(wn + 16 * i) * ASTR + ks], ASTR);
                wmma::load_matrix_sync(blo[i], &sWlo[(wn + 16 * i) * ASTR + ks], ASTR);
            }
#pragma unroll
            for (int i = 0; i < 2; i++)
#pragma unroll
                for (int j = 0; j < 2; j++) {
                    wmma::mma_sync(acc[i][j], ahi[i], bhi[j], acc[i][j]);
                    wmma::mma_sync(acc[i][j], ahi[i], blo[j], acc[i][j]);
                    wmma::mma_sync(acc[i][j], alo[i], bhi[j], acc[i][j]);
                }
        }
        __syncthreads();
    }

#pragma unroll
    for (int i = 0; i < 2; i++)
#pragma unroll
        for (int j = 0; j < 2; j++)
            wmma::store_matrix_sync(C + (size_t)(bm + wm + 16 * i) * HC + bn + wn + 16 * j,
                                    acc[i][j], HC, wmma::mem_row_major);
}

// ---------------- CSR build (once per call, reused by both layers) ----------
__global__ void csr_count(const int* __restrict__ dst) {
    int e = blockIdx.x * blockDim.x + threadIdx.x;
    if (e < EE) atomicAdd(&g_deg[dst[e]], 1);
}

__global__ __launch_bounds__(1024) void csr_scan() {
    __shared__ int ssum[1024];
    const int T = 1024;
    const int per = (NN + T - 1) / T;
    int t = threadIdx.x;
    int base = t * per;
    int sum = 0;
    for (int i = 0; i < per; i++) {
        int idx = base + i;
        if (idx < NN) sum += g_deg[idx];
    }
    ssum[t] = sum;
    __syncthreads();
    for (int off = 1; off < T; off <<= 1) {
        int u = (t >= off) ? ssum[t - off] : 0;
        __syncthreads();
        ssum[t] += u;
        __syncthreads();
    }
    int run = ssum[t] - sum;
    for (int i = 0; i < per; i++) {
        int idx = base + i;
        if (idx < NN) {
            g_off[idx] = run;
            g_cur[idx] = run;
            run += g_deg[idx];
        }
    }
    if (t == T - 1) g_off[NN] = run;
}

__global__ void csr_scatter(const int* __restrict__ src,
                            const int* __restrict__ dst,
                            const float* __restrict__ ea) {
    int e = blockIdx.x * blockDim.x + threadIdx.x;
    if (e >= EE) return;
    int d = dst[e];
    int p = atomicAdd(&g_cur[d], 1);
    float4 r;
    r.x = __int_as_float(src[e]);
    r.y = ea[(size_t)e * 3 + 0];
    r.z = ea[(size_t)e * 3 + 1];
    r.w = ea[(size_t)e * 3 + 2];
    g_edge[p] = r;
}

// ---------------- degree-descending node order -------------------------------
__device__ __forceinline__ int deg_bucket(int deg) {
    return (deg > 63) ? 0 : (63 - deg);
}
__global__ void deg_hist() {
    __shared__ int sh[64];
    int t = threadIdx.x;
    if (t < 64) sh[t] = 0;
    __syncthreads();
    int n = blockIdx.x * blockDim.x + t;
    if (n < NN) atomicAdd(&sh[deg_bucket(g_off[n + 1] - g_off[n])], 1);
    __syncthreads();
    if (t < 64 && sh[t]) atomicAdd(&g_dhist[t], sh[t]);
}
__global__ void deg_scan() {
    __shared__ int s[64];
    int t = threadIdx.x;
    int my = g_dhist[t];
    s[t] = my;
    __syncthreads();
    for (int off = 1; off < 64; off <<= 1) {
        int u = (t >= off) ? s[t - off] : 0;
        __syncthreads();
        s[t] += u;
        __syncthreads();
    }
    g_dcur[t] = s[t] - my;
}
__global__ void deg_scatter() {
    int n = blockIdx.x * blockDim.x + threadIdx.x;
    if (n >= NN) return;
    int pos = atomicAdd(&g_dcur[deg_bucket(g_off[n + 1] - g_off[n])], 1);
    g_nodeord[pos] = n;
}

// ---- fused gather pass: one warp per dst node, lane = head*8 + group --------
// (R7 version — proven fastest.) Softmax ratio is shift-invariant and logits
// are O(10), so exp() without the segment-max shift is exact enough in fp32.
__global__ __launch_bounds__(256) void node_gather(
    const float* __restrict__ We,       // [256,3]
    const float* __restrict__ att,      // [256] flat h*64+c
    const float* __restrict__ bias,     // [64]
    const float* __restrict__ prelu,    // [64]
    float* __restrict__ out, int mode)
{
    int tid = threadIdx.x;
    int widx = blockIdx.x * 8 + (tid >> 5);
    if (widx >= NN) return;
    int lane = tid & 31;
    int n = g_nodeord[widx];
    int f = lane * 8;

    float wa[8], wb[8], wc[8], av[8];
    {
        const float4* wp = reinterpret_cast<const float4*>(We + f * 3);
        float4 q[6];
#pragma unroll
        for (int i = 0; i < 6; i++) q[i] = __ldg(wp + i);
        const float* qf = (const float*)q;
#pragma unroll
        for (int i = 0; i < 8; i++) {
            wa[i] = qf[3 * i + 0];
            wb[i] = qf[3 * i + 1];
            wc[i] = qf[3 * i + 2];
        }
        float4 A0 = __ldg((const float4*)(att + f));
        float4 A1 = __ldg((const float4*)(att + f + 4));
        av[0] = A0.x; av[1] = A0.y; av[2] = A0.z; av[3] = A0.w;
        av[4] = A1.x; av[5] = A1.y; av[6] = A1.z; av[7] = A1.w;
    }

    const float4* xrp = reinterpret_cast<const float4*>(g_XR) + (size_t)n * (HC / 4);
    float4 R0 = __ldg(xrp + 2 * lane);
    float4 R1 = __ldg(xrp + 2 * lane + 1);
    float xr[8] = { R0.x, R0.y, R0.z, R0.w, R1.x, R1.y, R1.z, R1.w };

    int o0 = g_off[n];
    int o1 = g_off[n + 1];

    float acc[8] = { 0.f, 0.f, 0.f, 0.f, 0.f, 0.f, 0.f, 0.f };
    float den = 0.f;

    for (int j = o0; j < o1; j++) {
        float4 er = __ldg(&g_edge[j]);
        int s = __float_as_int(er.x);
        const float4* xlp = reinterpret_cast<const float4*>(g_XL) + (size_t)s * (HC / 4);
        float4 X0 = __ldg(xlp + 2 * lane);
        float4 X1 = __ldg(xlp + 2 * lane + 1);
        float xl[8] = { X0.x, X0.y, X0.z, X0.w, X1.x, X1.y, X1.z, X1.w };

        float p = 0.f;
#pragma unroll
        for (int i = 0; i < 8; i++) {
            float z = lrelu(xl[i] + xr[i] +
                            fmaf(er.w, wc[i], fmaf(er.z, wb[i], er.y * wa[i])));
            p = fmaf(z, av[i], p);
        }
        p += __shfl_xor_sync(0xffffffffu, p, 4);
        p += __shfl_xor_sync(0xffffffffu, p, 2);
        p += __shfl_xor_sync(0xffffffffu, p, 1);
        float w = __expf(p);
        den += w;
#pragma unroll
        for (int i = 0; i < 8; i++) acc[i] = fmaf(w, xl[i], acc[i]);
    }

    float inv = den > 0.f ? __frcp_rn(den) : 0.f;
#pragma unroll
    for (int i = 0; i < 8; i++) acc[i] *= inv;

#pragma unroll
    for (int i = 0; i < 8; i++) {
        acc[i] += __shfl_xor_sync(0xffffffffu, acc[i], 8);
        acc[i] += __shfl_xor_sync(0xffffffffu, acc[i], 16);
    }

    if (lane < 8) {
        int c = lane * 8;
        float4 b0 = __ldg((const float4*)(bias + c));
        float4 b1 = __ldg((const float4*)(bias + c + 4));
        float v[8];
        v[0] = fmaf(0.25f, acc[0], b0.x);
        v[1] = fmaf(0.25f, acc[1], b0.y);
        v[2] = fmaf(0.25f, acc[2], b0.z);
        v[3] = fmaf(0.25f, acc[3], b0.w);
        v[4] = fmaf(0.25f, acc[4], b1.x);
        v[5] = fmaf(0.25f, acc[5], b1.y);
        v[6] = fmaf(0.25f, acc[6], b1.z);
        v[7] = fmaf(0.25f, acc[7], b1.w);
        if (mode == 0) {
            float4* p = (float4*)(g_H1 + (size_t)n * CC + c);
            p[0] = make_float4(v[0], v[1], v[2], v[3]);
            p[1] = make_float4(v[4], v[5], v[6], v[7]);
        } else {
            float4 p0 = __ldg((const float4*)(prelu + c));
            float4 p1 = __ldg((const float4*)(prelu + c + 4));
            float pw[8] = { p0.x, p0.y, p0.z, p0.w, p1.x, p1.y, p1.z, p1.w };
#pragma unroll
            for (int i = 0; i < 8; i++) v[i] = (v[i] >= 0.f) ? v[i] : pw[i] * v[i];
            float4* p = (float4*)(out + (size_t)n * CC + c);
            p[0] = make_float4(v[0], v[1], v[2], v[3]);
            p[1] = make_float4(v[4], v[5], v[6], v[7]);
        }
    }
}

// ---------------- launch -----------------------------------------------------
extern "C" void kernel_launch(void* const* d_in, const int* in_sizes, int n_in,
                              void* d_out, int out_size)
{
    const float* x     = (const float*)d_in[0];
    const int*   ei    = (const int*)  d_in[1];
    const float* eattr = (const float*)d_in[2];
    const float* Wl1   = (const float*)d_in[3];
    const float* Wr1   = (const float*)d_in[4];
    const float* We1   = (const float*)d_in[5];
    const float* att1  = (const float*)d_in[6];
    const float* b1    = (const float*)d_in[7];
    const float* Wl2   = (const float*)d_in[8];
    const float* Wr2   = (const float*)d_in[9];
    const float* We2   = (const float*)d_in[10];
    const float* att2  = (const float*)d_in[11];
    const float* b2    = (const float*)d_in[12];
    const float* prelu = (const float*)d_in[13];
    float* out = (float*)d_out;

    const int* src = ei;
    const int* dst = ei + EE;

    float *XL, *XR, *H1;
    __nv_bfloat16 *Ahi, *Alo, *Whi, *Wlo;
    void *degp, *dhistp;
    cudaGetSymbolAddress((void**)&XL, g_XL);
    cudaGetSymbolAddress((void**)&XR, g_XR);
    cudaGetSymbolAddress((void**)&H1, g_H1);
    cudaGetSymbolAddress((void**)&Ahi, g_Ahi);
    cudaGetSymbolAddress((void**)&Alo, g_Alo);
    cudaGetSymbolAddress((void**)&Whi, g_Whi);
    cudaGetSymbolAddress((void**)&Wlo, g_Wlo);
    cudaGetSymbolAddress(&degp, g_deg);
    cudaGetSymbolAddress(&dhistp, g_dhist);

    cudaFuncSetAttribute(gemm_wmma, cudaFuncAttributeMaxDynamicSharedMemorySize,
                         GSMEM);

    dim3 ggrid(8, NN_PAD / BM);            // 8 x 391
    const int egrid = (EE + 255) / 256;
    const int ngrid = (NN + 7) / 8;
    const int vgrid = (NN + 255) / 256;

    // ---- CSR build + degree-sorted node order (shared by both layers) ----
    cudaMemsetAsync(degp, 0, NN * sizeof(int));
    cudaMemsetAsync(dhistp, 0, 64 * sizeof(int));
    csr_count<<<egrid, 256>>>(dst);
    csr_scan<<<1, 1024>>>();
    csr_scatter<<<egrid, 256>>>(src, dst, eattr);
    deg_hist<<<vgrid, 256>>>();
    deg_scan<<<1, 64>>>();
    deg_scatter<<<vgrid, 256>>>();

    // ---- layer 1 (K=128) ----
    {
        const int K = 128;
        int aq_real = NN * K / 4, aq_tot = NN_PAD * K / 4;
        int wq = 256 * K / 4;
        split_mat<<<(aq_tot + 255) / 256, 256>>>(x, Ahi, Alo, aq_real, aq_tot);
        split_mat<<<(wq + 255) / 256, 256>>>(Wl1, Whi, Wlo, wq, wq);
        split_mat<<<(wq + 255) / 256, 256>>>(Wr1, Whi + (size_t)256 * K,
                                             Wlo + (size_t)256 * K, wq, wq);
        gemm_wmma<<<ggrid, 256, GSMEM>>>(Ahi, Alo, Whi, Wlo, XL, XR, K);
        node_gather<<<ngrid, 256>>>(We1, att1, b1, prelu, out, 0);
    }

    // ---- layer 2 (K=64) ----
    {
        const int K = 64;
        int aq_real = NN * K / 4, aq_tot = NN_PAD * K / 4;
        int wq = 256 * K / 4;
        split_mat<<<(aq_tot + 255) / 256, 256>>>(H1, Ahi, Alo, aq_real, aq_tot);
        split_mat<<<(wq + 255) / 256, 256>>>(Wl2, Whi, Wlo, wq, wq);
        split_mat<<<(wq + 255) / 256, 256>>>(Wr2, Whi + (size_t)256 * K,
                                             Wlo + (size_t)256 * K, wq, wq);
        gemm_wmma<<<ggrid, 256, GSMEM>>>(Ahi, Alo, Whi, Wlo, XL, XR, K);
        node_gather<<<ngrid, 256>>>(We2, att2, b2, prelu, out, 1);
    }
}